// round 8
// baseline (speedup 1.0000x reference)
#include <cuda_runtime.h>
#include <math.h>

#define TSTEPS 512
#define BATCH  64
#define DIN    256
#define HID    512
#define DOUT   256
#define G4H    2048
#define NBLK   128

typedef unsigned long long ull;

// ---------------- scratch ----------------
__device__ float d_Genc[(size_t)TSTEPS * G4H * BATCH];    // [t][gate*H+u][b]
__device__ float d_Gdec[(size_t)TSTEPS * G4H * BATCH];
__device__ float d_hbuf[2][HID * BATCH];                  // ull view: [kpair][b]
__device__ float d_cbuf[HID * BATCH];                     // [u][b]
__device__ float d_hs[(size_t)TSTEPS * HID * BATCH];      // [t][u][b]
__device__ float d_logits[(size_t)TSTEPS * BATCH * DOUT]; // [t][b][n]
__device__ int d_wr[NBLK];   // wr[b] = s  <=>  h_s from block b is published
__device__ int d_rd[NBLK];   // rd[b] = s  <=>  block b finished READING h_s

// ---------------- helpers ----------------
__device__ __forceinline__ void fma2(ull& a, ull x, ull y) {
    asm("fma.rn.f32x2 %0, %1, %2, %3;" : "=l"(a) : "l"(x), "l"(y), "l"(a));
}
__device__ __forceinline__ void fadd2(ull& a, ull x) {
    asm("add.rn.f32x2 %0, %1, %2;" : "=l"(a) : "l"(a), "l"(x));
}
__device__ __forceinline__ ull pack2(float lo, float hi) {
    ull r; asm("mov.b64 %0, {%1, %2};" : "=l"(r) : "f"(lo), "f"(hi)); return r;
}
__device__ __forceinline__ float sum2(ull v) {
    float lo, hi; asm("mov.b64 {%0, %1}, %2;" : "=f"(lo), "=f"(hi) : "l"(v));
    return lo + hi;
}
__device__ __forceinline__ ull ldcg64(const ull* p) {
    ull v; asm volatile("ld.global.cg.u64 %0, [%1];" : "=l"(v) : "l"(p)); return v;
}
__device__ __forceinline__ int ld_acq(const int* p) {
    int v; asm volatile("ld.acquire.gpu.global.s32 %0, [%1];" : "=r"(v) : "l"(p) : "memory");
    return v;
}
__device__ __forceinline__ void st_rel(int* p, int v) {
    asm volatile("st.release.gpu.global.s32 [%0], %1;" :: "l"(p), "r"(v) : "memory");
}
__device__ __forceinline__ float fsig(float x) {
    return __fdividef(1.0f, 1.0f + __expf(-x));
}
__device__ __forceinline__ float ftanh(float x) {
    float e = __expf(2.0f * x);                 // inf-safe
    return 1.0f - __fdividef(2.0f, e + 1.0f);
}

// ---------------- init: pack initial h/c, reset flags ----------------
__global__ __launch_bounds__(256) void init_state(const float* __restrict__ h0,
                                                  const float* __restrict__ c0) {
    int i = blockIdx.x * blockDim.x + threadIdx.x;
    if (i < NBLK) { d_wr[i] = 0; d_rd[i] = -1; }
    if (i >= HID * BATCH) return;
    int b = i >> 9;                 // h0 layout [1][B][H]
    int u = i & 511;
    d_hbuf[0][((u >> 1) * BATCH + b) * 2 + (u & 1)] = h0[i];
    d_cbuf[u * BATCH + b] = c0[i];
}

// ---------------- unified register-blocked GEMM ----------------
__global__ __launch_bounds__(256, 2) void gemm_kernel(
    const float* __restrict__ X, const float* __restrict__ W,
    const float* __restrict__ bias, float* __restrict__ Out,
    int Ntot, int K, int kchunks, int dec_shift, int x_kb, int out_bn) {
    __shared__ ull Wt[16 * 130];
    __shared__ ull Xt[16 * 66];

    int t  = blockIdx.y;
    int n0 = blockIdx.x * 128;
    int tid = threadIdx.x;
    int tx = tid & 15, ty = tid >> 4;

    ull acc[8][4];
#pragma unroll
    for (int i = 0; i < 8; i++)
#pragma unroll
        for (int j = 0; j < 4; j++) acc[i][j] = 0ull;

    for (int ch = 0; ch < kchunks; ch++) {
        for (int idx = tid; idx < 2048; idx += 256) {
            int kk = idx & 15, n = idx >> 4;
            Wt[kk * 130 + n] = *(const ull*)(W + (size_t)(n0 + n) * K + ch * 32 + kk * 2);
        }
        if (x_kb) {
            for (int idx = tid; idx < 1024; idx += 256) {
                int b = idx & 63, kk = idx >> 6;
                int kg = ch * 32 + kk * 2;
                Xt[kk * 66 + b] = pack2(X[((size_t)t * K + kg) * 64 + b],
                                        X[((size_t)t * K + kg + 1) * 64 + b]);
            }
        } else {
            bool zero = (dec_shift && t == 0);
            int trow = t - dec_shift;
            for (int idx = tid; idx < 1024; idx += 256) {
                int kk = idx & 15, b = idx >> 4;
                Xt[kk * 66 + b] = zero ? 0ull
                    : *(const ull*)(X + ((size_t)trow * 64 + b) * K + ch * 32 + kk * 2);
            }
        }
        __syncthreads();
#pragma unroll
        for (int kk = 0; kk < 16; kk++) {
            ulonglong2 xv0 = *(const ulonglong2*)&Xt[kk * 66 + tx * 4];
            ulonglong2 xv1 = *(const ulonglong2*)&Xt[kk * 66 + tx * 4 + 2];
            ull xs0 = xv0.x, xs1 = xv0.y, xs2 = xv1.x, xs3 = xv1.y;
#pragma unroll
            for (int q = 0; q < 4; q++) {
                ulonglong2 wv = *(const ulonglong2*)&Wt[kk * 130 + ty * 8 + 2 * q];
                fma2(acc[2 * q][0], wv.x, xs0);
                fma2(acc[2 * q][1], wv.x, xs1);
                fma2(acc[2 * q][2], wv.x, xs2);
                fma2(acc[2 * q][3], wv.x, xs3);
                fma2(acc[2 * q + 1][0], wv.y, xs0);
                fma2(acc[2 * q + 1][1], wv.y, xs1);
                fma2(acc[2 * q + 1][2], wv.y, xs2);
                fma2(acc[2 * q + 1][3], wv.y, xs3);
            }
        }
        __syncthreads();
    }

    if (out_bn) {
        float bb[8];
#pragma unroll
        for (int i = 0; i < 8; i++) bb[i] = bias[n0 + ty * 8 + i];
#pragma unroll
        for (int j = 0; j < 4; j++) {
            int b = tx * 4 + j;
            float v[8];
#pragma unroll
            for (int i = 0; i < 8; i++) v[i] = sum2(acc[i][j]) + bb[i];
            float* op = Out + ((size_t)t * 64 + b) * Ntot + n0 + ty * 8;
            *(float4*)op       = make_float4(v[0], v[1], v[2], v[3]);
            *(float4*)(op + 4) = make_float4(v[4], v[5], v[6], v[7]);
        }
    } else {
#pragma unroll
        for (int i = 0; i < 8; i++) {
            int n = n0 + ty * 8 + i;
            float bb = bias[n];
            float4 o = make_float4(sum2(acc[i][0]) + bb, sum2(acc[i][1]) + bb,
                                   sum2(acc[i][2]) + bb, sum2(acc[i][3]) + bb);
            *(float4*)(Out + ((size_t)t * Ntot + n) * 64 + tx * 4) = o;
        }
    }
}

// ---------------- persistent recurrent LSTM: distributed flag sync ----------------
// 512 threads. Block owns 4 units (16 gate rows). Warp w reduces kpairs
// [16w,16w+16), depending only on producer blocks [8w,8w+8) -> warp-local
// forward sync. Anti-dep polled by threads 384..511 concurrently with the
// reduction epilogue. Global step s = sbase + t keeps flags monotonic
// across encoder -> decoder.
__global__ __launch_bounds__(512) void recur_kernel(const float* __restrict__ Whh,
                                                    int which, int sbase) {
    extern __shared__ ull sm[];
    ull* ws  = sm;            // [kp][16 rows]          4096 ull = 32 KB
    ull* red = sm + 4096;     // [(r*64+b)*17 + w]      17408 ull = 136 KB

    const float* __restrict__ G = which ? d_Gdec : d_Genc;
    int tid = threadIdx.x;
    int w = tid >> 5, l = tid & 31;
    int ul = tid >> 6, b = tid & 63;       // epilogue mapping (tid < 256)
    int u0 = blockIdx.x * 4;
    int u = u0 + ul;

    // weights: layout [kpair][row], row = gate*4 + unit
    for (int idx = tid; idx < 4096; idx += 512) {
        int kp = idx >> 4, r = idx & 15;
        int g = r >> 2, uu = r & 3;
        ws[idx] = *(const ull*)(Whh + ((size_t)(g * HID + u0 + uu)) * HID + kp * 2);
    }
    float c = (tid < 256) ? d_cbuf[u * BATCH + b] : 0.0f;
    int kbase = w * 16;
    __syncthreads();

    for (int t = 0; t < TSTEPS; t++) {
        int s = sbase + t;
        // prefetch precomputed x-projection gates (independent of sync)
        float pi = 0.f, pf = 0.f, pg = 0.f, po = 0.f;
        if (tid < 256) {
            size_t gb = ((size_t)t * G4H + u) * BATCH + b;
            pi = G[gb];
            pf = G[gb + (size_t)512 * 64];
            pg = G[gb + (size_t)1024 * 64];
            po = G[gb + (size_t)1536 * 64];
        }

        // forward sync: warp w waits for its 8 producer blocks to publish h_s
        if (l < 8) { while (ld_acq(&d_wr[8 * w + l]) < s) { } }
        __syncwarp();

        const ull* hsrc = (const ull*)d_hbuf[s & 1];
        ull acc[16][2];
#pragma unroll
        for (int r = 0; r < 16; r++) { acc[r][0] = 0ull; acc[r][1] = 0ull; }

        ull hb[2][2][2];   // [parity][kp-in-chunk][half]
#pragma unroll
        for (int i = 0; i < 2; i++) {
            hb[0][i][0] = ldcg64(hsrc + (kbase + i) * 64 + l);
            hb[0][i][1] = ldcg64(hsrc + (kbase + i) * 64 + 32 + l);
        }
#pragma unroll
        for (int ch = 0; ch < 8; ch++) {
            int cur = ch & 1, nxt = cur ^ 1;
            if (ch < 7) {
#pragma unroll
                for (int i = 0; i < 2; i++) {
                    int kp = kbase + (ch + 1) * 2 + i;
                    hb[nxt][i][0] = ldcg64(hsrc + kp * 64 + l);
                    hb[nxt][i][1] = ldcg64(hsrc + kp * 64 + 32 + l);
                }
            }
#pragma unroll
            for (int i = 0; i < 2; i++) {
                const ulonglong2* wp = (const ulonglong2*)(ws + (size_t)(kbase + ch * 2 + i) * 16);
                ull h0 = hb[cur][i][0], h1 = hb[cur][i][1];
#pragma unroll
                for (int rp = 0; rp < 8; rp++) {
                    ulonglong2 wv = wp[rp];
                    fma2(acc[2 * rp][0], wv.x, h0);
                    fma2(acc[2 * rp][1], wv.x, h1);
                    fma2(acc[2 * rp + 1][0], wv.y, h0);
                    fma2(acc[2 * rp + 1][1], wv.y, h1);
                }
            }
        }
        // partials -> smem (stride 17: 2-way write conflicts, scalar 8B stores)
#pragma unroll
        for (int r = 0; r < 16; r++) {
            red[(size_t)(r * 64 + l) * 17 + w]      = acc[r][0];
            red[(size_t)(r * 64 + 32 + l) * 17 + w] = acc[r][1];
        }
        __syncthreads();                       // all reads of h_s complete
        if (tid == 0) st_rel(&d_rd[blockIdx.x], s);

        float h = 0.0f;
        if (tid < 256) {
            // reduce 16 warp-partials per gate (scalar ull loads: 8B aligned)
            float gate[4];
#pragma unroll
            for (int g = 0; g < 4; g++) {
                int r = g * 4 + ul;
                const ull* rp_ = red + (size_t)(r * 64 + b) * 17;
                ull a0 = rp_[0];  fadd2(a0, rp_[1]);  fadd2(a0, rp_[2]);  fadd2(a0, rp_[3]);
                ull a1 = rp_[4];  fadd2(a1, rp_[5]);  fadd2(a1, rp_[6]);  fadd2(a1, rp_[7]);
                ull a2 = rp_[8];  fadd2(a2, rp_[9]);  fadd2(a2, rp_[10]); fadd2(a2, rp_[11]);
                ull a3 = rp_[12]; fadd2(a3, rp_[13]); fadd2(a3, rp_[14]); fadd2(a3, rp_[15]);
                fadd2(a0, a1); fadd2(a2, a3); fadd2(a0, a2);
                gate[g] = sum2(a0);
            }
            float iv = fsig(gate[0] + pi);
            float fv = fsig(gate[1] + pf);
            float gv = ftanh(gate[2] + pg);
            float ov = fsig(gate[3] + po);
            c = fv * c + iv * gv;
            h = ov * ftanh(c);
        } else if (tid >= 384) {
            // anti-dep: all blocks must have finished READING h_{s-1}
            // (buffer (s+1)&1 currently holds h_{s-1})
            int i = tid - 384;
            while (ld_acq(&d_rd[i]) < s - 1) { }
        }
        __syncthreads();                       // anti-dep confirmed before stores

        if (tid < 256) {
            d_hbuf[(s + 1) & 1][((u >> 1) * 64 + b) * 2 + (u & 1)] = h;
            if (which) d_hs[((size_t)t * HID + u) * 64 + b] = h;
        }
        __syncthreads();                       // h stores done block-wide
        if (tid == 0) { __threadfence(); st_rel(&d_wr[blockIdx.x], s + 1); }
    }
    if (tid < 256) d_cbuf[u * 64 + b] = c;     // encoder -> decoder handoff
}

// ---------------- softmax over last dim (256), one warp per (t,b) row ----------------
__global__ __launch_bounds__(256) void softmax_kernel(float* __restrict__ out) {
    int row = blockIdx.x * 8 + (threadIdx.x >> 5);
    if (row >= TSTEPS * BATCH) return;
    int lane = threadIdx.x & 31;
    const float* lp = d_logits + (size_t)row * DOUT;
    float v[8];
    float m = -INFINITY;
#pragma unroll
    for (int i = 0; i < 8; i++) { v[i] = lp[lane + 32 * i]; m = fmaxf(m, v[i]); }
#pragma unroll
    for (int o = 16; o > 0; o >>= 1) m = fmaxf(m, __shfl_xor_sync(0xffffffffu, m, o));
    float s = 0.0f;
#pragma unroll
    for (int i = 0; i < 8; i++) { v[i] = expf(v[i] - m); s += v[i]; }
#pragma unroll
    for (int o = 16; o > 0; o >>= 1) s += __shfl_xor_sync(0xffffffffu, s, o);
    float inv = 1.0f / s;
    float* op = out + (size_t)row * DOUT;
#pragma unroll
    for (int i = 0; i < 8; i++) op[lane + 32 * i] = v[i] * inv;
}

// ---------------- launch ----------------
extern "C" void kernel_launch(void* const* d_in, const int* in_sizes, int n_in,
                              void* d_out, int out_size) {
    const float* x      = (const float*)d_in[0];
    const float* target = (const float*)d_in[1];
    const float* h0     = (const float*)d_in[2];
    const float* c0     = (const float*)d_in[3];
    const float* eWih   = (const float*)d_in[4];
    const float* eWhh   = (const float*)d_in[5];
    const float* eb     = (const float*)d_in[6];
    const float* dWih   = (const float*)d_in[7];
    const float* dWhh   = (const float*)d_in[8];
    const float* db     = (const float*)d_in[9];
    const float* fcW    = (const float*)d_in[10];
    const float* fcb    = (const float*)d_in[11];
    float* out = (float*)d_out;

    const int smem_recur = (4096 + 17408) * 8;   // 172032 B
    cudaFuncSetAttribute(recur_kernel, cudaFuncAttributeMaxDynamicSharedMemorySize, smem_recur);

    init_state<<<128, 256>>>(h0, c0);

    float* genc; cudaGetSymbolAddress((void**)&genc, d_Genc);
    float* gdec; cudaGetSymbolAddress((void**)&gdec, d_Gdec);
    float* ghs;  cudaGetSymbolAddress((void**)&ghs,  d_hs);
    float* glog; cudaGetSymbolAddress((void**)&glog, d_logits);

    gemm_kernel<<<dim3(16, TSTEPS), 256>>>(x,      eWih, eb, genc, G4H, DIN, DIN / 32, 0, 0, 0);
    gemm_kernel<<<dim3(16, TSTEPS), 256>>>(target, dWih, db, gdec, G4H, DOUT, DOUT / 32, 1, 0, 0);

    recur_kernel<<<NBLK, 512, smem_recur>>>(eWhh, 0, 0);
    recur_kernel<<<NBLK, 512, smem_recur>>>(dWhh, 1, TSTEPS);

    gemm_kernel<<<dim3(2, TSTEPS), 256>>>(ghs, fcW, fcb, glog, DOUT, HID, HID / 32, 0, 1, 1);
    softmax_kernel<<<(TSTEPS * BATCH + 7) / 8, 256>>>(out);
}

// round 9
// speedup vs baseline: 1.3241x; 1.3241x over previous
#include <cuda_runtime.h>
#include <math.h>

#define TSTEPS 512
#define BATCH  64
#define DIN    256
#define HID    512
#define DOUT   256
#define G4H    2048
#define NBLK   128
#define NCH    4      // batch chains
#define BCH    16     // batches per chain

typedef unsigned long long ull;

// ---------------- scratch ----------------
__device__ float d_Genc[(size_t)TSTEPS * G4H * BATCH];    // [t][gate*512+u][b]
__device__ float d_Gdec[(size_t)TSTEPS * G4H * BATCH];
__device__ float d_hq[NCH][2][256 * BCH * 2];             // [chain][parity][kpair][b16][2] floats
__device__ float d_cbuf[HID * BATCH];                     // [u][b]
__device__ float d_hs[(size_t)TSTEPS * HID * BATCH];      // [t][u][b]
__device__ float d_logits[(size_t)TSTEPS * BATCH * DOUT]; // [t][b][n]
__device__ unsigned d_cnt[NCH * 32];                      // stride-32 ints: one line per chain
__device__ volatile int d_epoch[NCH * 32];

// ---------------- helpers ----------------
__device__ __forceinline__ void fma2(ull& a, ull x, ull y) {
    asm("fma.rn.f32x2 %0, %1, %2, %3;" : "=l"(a) : "l"(x), "l"(y), "l"(a));
}
__device__ __forceinline__ void fadd2(ull& a, ull x) {
    asm("add.rn.f32x2 %0, %1, %2;" : "=l"(a) : "l"(a), "l"(x));
}
__device__ __forceinline__ ull pack2(float lo, float hi) {
    ull r; asm("mov.b64 %0, {%1, %2};" : "=l"(r) : "f"(lo), "f"(hi)); return r;
}
__device__ __forceinline__ float sum2(ull v) {
    float lo, hi; asm("mov.b64 {%0, %1}, %2;" : "=f"(lo), "=f"(hi) : "l"(v));
    return lo + hi;
}
__device__ __forceinline__ ull ldcg64(const ull* p) {
    ull v; asm volatile("ld.global.cg.u64 %0, [%1];" : "=l"(v) : "l"(p)); return v;
}
__device__ __forceinline__ int ld_acq(const volatile int* p) {
    int v; asm volatile("ld.acquire.gpu.global.s32 %0, [%1];" : "=r"(v) : "l"(p) : "memory");
    return v;
}
__device__ __forceinline__ void st_rel(volatile int* p, int v) {
    asm volatile("st.release.gpu.global.s32 [%0], %1;" :: "l"(p), "r"(v) : "memory");
}
__device__ __forceinline__ void barx(int id) {
    asm volatile("bar.sync %0, 128;" :: "r"(id) : "memory");
}
__device__ __forceinline__ float fsig(float x) {
    return __fdividef(1.0f, 1.0f + __expf(-x));
}
__device__ __forceinline__ float ftanh(float x) {
    float e = __expf(2.0f * x);                 // inf-safe
    return 1.0f - __fdividef(2.0f, e + 1.0f);
}

// ---------------- init: pack initial h/c per chain, reset sync state ----------------
__global__ __launch_bounds__(256) void init_state(const float* __restrict__ h0,
                                                  const float* __restrict__ c0) {
    int i = blockIdx.x * blockDim.x + threadIdx.x;
    if (i < NCH) { d_cnt[i * 32] = 0u; d_epoch[i * 32] = 0; }
    if (i >= HID * BATCH) return;
    int b = i >> 9;                 // h0 layout [1][B][H]
    int u = i & 511;
    int q = b >> 4, b16 = b & 15;
    d_hq[q][0][((u >> 1) * BCH + b16) * 2 + (u & 1)] = h0[i];
    d_cbuf[u * BATCH + b] = c0[i];
}

// ---------------- unified register-blocked GEMM (proven in R3) ----------------
__global__ __launch_bounds__(256, 2) void gemm_kernel(
    const float* __restrict__ X, const float* __restrict__ W,
    const float* __restrict__ bias, float* __restrict__ Out,
    int Ntot, int K, int kchunks, int dec_shift, int x_kb, int out_bn) {
    __shared__ ull Wt[16 * 130];
    __shared__ ull Xt[16 * 66];

    int t  = blockIdx.y;
    int n0 = blockIdx.x * 128;
    int tid = threadIdx.x;
    int tx = tid & 15, ty = tid >> 4;

    ull acc[8][4];
#pragma unroll
    for (int i = 0; i < 8; i++)
#pragma unroll
        for (int j = 0; j < 4; j++) acc[i][j] = 0ull;

    for (int ch = 0; ch < kchunks; ch++) {
        for (int idx = tid; idx < 2048; idx += 256) {
            int kk = idx & 15, n = idx >> 4;
            Wt[kk * 130 + n] = *(const ull*)(W + (size_t)(n0 + n) * K + ch * 32 + kk * 2);
        }
        if (x_kb) {
            for (int idx = tid; idx < 1024; idx += 256) {
                int b = idx & 63, kk = idx >> 6;
                int kg = ch * 32 + kk * 2;
                Xt[kk * 66 + b] = pack2(X[((size_t)t * K + kg) * 64 + b],
                                        X[((size_t)t * K + kg + 1) * 64 + b]);
            }
        } else {
            bool zero = (dec_shift && t == 0);
            int trow = t - dec_shift;
            for (int idx = tid; idx < 1024; idx += 256) {
                int kk = idx & 15, b = idx >> 4;
                Xt[kk * 66 + b] = zero ? 0ull
                    : *(const ull*)(X + ((size_t)trow * 64 + b) * K + ch * 32 + kk * 2);
            }
        }
        __syncthreads();
#pragma unroll
        for (int kk = 0; kk < 16; kk++) {
            ulonglong2 xv0 = *(const ulonglong2*)&Xt[kk * 66 + tx * 4];
            ulonglong2 xv1 = *(const ulonglong2*)&Xt[kk * 66 + tx * 4 + 2];
            ull xs0 = xv0.x, xs1 = xv0.y, xs2 = xv1.x, xs3 = xv1.y;
#pragma unroll
            for (int q = 0; q < 4; q++) {
                ulonglong2 wv = *(const ulonglong2*)&Wt[kk * 130 + ty * 8 + 2 * q];
                fma2(acc[2 * q][0], wv.x, xs0);
                fma2(acc[2 * q][1], wv.x, xs1);
                fma2(acc[2 * q][2], wv.x, xs2);
                fma2(acc[2 * q][3], wv.x, xs3);
                fma2(acc[2 * q + 1][0], wv.y, xs0);
                fma2(acc[2 * q + 1][1], wv.y, xs1);
                fma2(acc[2 * q + 1][2], wv.y, xs2);
                fma2(acc[2 * q + 1][3], wv.y, xs3);
            }
        }
        __syncthreads();
    }

    if (out_bn) {
        float bb[8];
#pragma unroll
        for (int i = 0; i < 8; i++) bb[i] = bias[n0 + ty * 8 + i];
#pragma unroll
        for (int j = 0; j < 4; j++) {
            int b = tx * 4 + j;
            float v[8];
#pragma unroll
            for (int i = 0; i < 8; i++) v[i] = sum2(acc[i][j]) + bb[i];
            float* op = Out + ((size_t)t * 64 + b) * Ntot + n0 + ty * 8;
            *(float4*)op       = make_float4(v[0], v[1], v[2], v[3]);
            *(float4*)(op + 4) = make_float4(v[4], v[5], v[6], v[7]);
        }
    } else {
#pragma unroll
        for (int i = 0; i < 8; i++) {
            int n = n0 + ty * 8 + i;
            float bb = bias[n];
            float4 o = make_float4(sum2(acc[i][0]) + bb, sum2(acc[i][1]) + bb,
                                   sum2(acc[i][2]) + bb, sum2(acc[i][3]) + bb);
            *(float4*)(Out + ((size_t)t * Ntot + n) * 64 + tx * 4) = o;
        }
    }
}

// ---------------- persistent recurrent LSTM: 4 interleaved batch chains ----------------
// 512 threads. Block owns 4 units (16 gate rows). Chain q (batches [16q,16q+16))
// runs on warps 4q..4q+3 (one per SMSP). Chains advance independently: while one
// chain waits on its cross-block epoch barrier, the other chains' warps keep the
// FMA pipe busy. Per chain: R3-style central counter (1 poller + 1 arriver per
// block) and a named barrier (id 1+q) scoped to its 128 threads.
__global__ __launch_bounds__(512) void recur_kernel(const float* __restrict__ Whh,
                                                    int which, int sbase) {
    extern __shared__ ull sm[];
    ull* ws  = sm;            // [kpair][16 rows]   4096 ull = 32 KB
    ull* red = sm + 4096;     // per chain: [(row*16+b16)*9 + slot], 2304 ull each

    const float* __restrict__ G = which ? d_Gdec : d_Genc;
    int tid = threadIdx.x;
    int w = tid >> 5, l = tid & 31;
    int q = w >> 2;                 // chain
    int wi = w & 3;                 // warp-in-chain (also SMSP)
    int b16 = l & 15, kh = l >> 4;  // FMA lane mapping
    int u0 = blockIdx.x * 4;
    int bid = blockIdx.x;

    // weights: [kpair][row], row = gate*4 + unit
    for (int idx = tid; idx < 4096; idx += 512) {
        int kp = idx >> 4, r = idx & 15;
        int g = r >> 2, uu = r & 3;
        ws[idx] = *(const ull*)(Whh + ((size_t)(g * HID + u0 + uu)) * HID + kp * 2);
    }
    __syncthreads();

    // epilogue mapping: warps wi<2 of each chain, 64 threads -> (ul, eb16)
    int e = wi * 32 + l;            // 0..127; epilogue iff wi<2 (e<64)
    int ul = (e >> 4) & 3, eb16 = e & 15;
    int u = u0 + ul;
    float c = (wi < 2) ? d_cbuf[u * BATCH + q * BCH + eb16] : 0.0f;

    ull* rq = red + q * 2304;
    int kbase = wi * 64 + kh * 32;
    const int barid = 1 + q;
    unsigned* cnt = &d_cnt[q * 32];
    volatile int* epoch = &d_epoch[q * 32];

    for (int t = 0; t < TSTEPS; t++) {
        int s = sbase + t;
        // wait: h_s published by all blocks for this chain (one poller)
        if (wi == 0 && l == 0) { while (ld_acq(epoch) < s) { } }
        barx(barid);

        // prefetch this chain's precomputed gate inputs (overlaps FMA)
        float pi = 0.f, pf = 0.f, pg = 0.f, po = 0.f;
        if (wi < 2) {
            size_t gb = ((size_t)t * G4H + u) * BATCH + q * BCH + eb16;
            pi = G[gb];
            pf = G[gb + (size_t)512 * 64];
            pg = G[gb + (size_t)1024 * 64];
            po = G[gb + (size_t)1536 * 64];
        }

        const ull* hsrc = (const ull*)d_hq[q][s & 1] + b16;
        ull acc[16];
#pragma unroll
        for (int r = 0; r < 16; r++) acc[r] = 0ull;

        ull hg[2][8];
#pragma unroll
        for (int j = 0; j < 8; j++) hg[0][j] = ldcg64(hsrc + (size_t)(kbase + j) * BCH);
#pragma unroll
        for (int g4 = 0; g4 < 4; g4++) {
            int cur = g4 & 1, nxt = cur ^ 1;
            if (g4 < 3) {
#pragma unroll
                for (int j = 0; j < 8; j++)
                    hg[nxt][j] = ldcg64(hsrc + (size_t)(kbase + (g4 + 1) * 8 + j) * BCH);
            }
#pragma unroll
            for (int j = 0; j < 8; j++) {
                const ulonglong2* wp = (const ulonglong2*)(ws + (size_t)(kbase + g4 * 8 + j) * 16);
                ull hv = hg[cur][j];
#pragma unroll
                for (int rp = 0; rp < 8; rp++) {
                    ulonglong2 wv = wp[rp];
                    fma2(acc[2 * rp],     wv.x, hv);
                    fma2(acc[2 * rp + 1], wv.y, hv);
                }
            }
        }
        // partials -> chain's reduction buffer
#pragma unroll
        for (int r = 0; r < 16; r++)
            rq[(size_t)(r * 16 + b16) * 9 + wi * 2 + kh] = acc[r];
        barx(barid);                        // partials ready; all h_s reads done

        if (wi < 2) {
            float gate[4];
#pragma unroll
            for (int g = 0; g < 4; g++) {
                int r = g * 4 + ul;
                const ull* rp_ = rq + (size_t)(r * 16 + eb16) * 9;
                ull a0 = rp_[0]; fadd2(a0, rp_[1]); fadd2(a0, rp_[2]); fadd2(a0, rp_[3]);
                ull a1 = rp_[4]; fadd2(a1, rp_[5]); fadd2(a1, rp_[6]); fadd2(a1, rp_[7]);
                fadd2(a0, a1);
                gate[g] = sum2(a0);
            }
            float iv = fsig(gate[0] + pi);
            float fv = fsig(gate[1] + pf);
            float gv = ftanh(gate[2] + pg);
            float ov = fsig(gate[3] + po);
            c = fv * c + iv * gv;
            float h = ov * ftanh(c);

            d_hq[q][(s + 1) & 1][((u >> 1) * BCH + eb16) * 2 + (u & 1)] = h;
            if (which) d_hs[((size_t)t * HID + u) * BATCH + q * BCH + eb16] = h;
        }
        barx(barid);                        // h_{s+1} stores issued chain-wide

        if (wi == 3 && l == 0) {
            __threadfence();
            unsigned old = atomicAdd(cnt, 1u);
            if (old == (unsigned)(NBLK * (s + 1)) - 1u) st_rel(epoch, s + 1);
        }
        (void)bid;
    }
    if (wi < 2) d_cbuf[u * BATCH + q * BCH + eb16] = c;   // enc -> dec handoff
}

// ---------------- softmax over last dim (256), one warp per (t,b) row ----------------
__global__ __launch_bounds__(256) void softmax_kernel(float* __restrict__ out) {
    int row = blockIdx.x * 8 + (threadIdx.x >> 5);
    if (row >= TSTEPS * BATCH) return;
    int lane = threadIdx.x & 31;
    const float* lp = d_logits + (size_t)row * DOUT;
    float v[8];
    float m = -INFINITY;
#pragma unroll
    for (int i = 0; i < 8; i++) { v[i] = lp[lane + 32 * i]; m = fmaxf(m, v[i]); }
#pragma unroll
    for (int o = 16; o > 0; o >>= 1) m = fmaxf(m, __shfl_xor_sync(0xffffffffu, m, o));
    float s = 0.0f;
#pragma unroll
    for (int i = 0; i < 8; i++) { v[i] = expf(v[i] - m); s += v[i]; }
#pragma unroll
    for (int o = 16; o > 0; o >>= 1) s += __shfl_xor_sync(0xffffffffu, s, o);
    float inv = 1.0f / s;
    float* op = out + (size_t)row * DOUT;
#pragma unroll
    for (int i = 0; i < 8; i++) op[lane + 32 * i] = v[i] * inv;
}

// ---------------- launch ----------------
extern "C" void kernel_launch(void* const* d_in, const int* in_sizes, int n_in,
                              void* d_out, int out_size) {
    const float* x      = (const float*)d_in[0];
    const float* target = (const float*)d_in[1];
    const float* h0     = (const float*)d_in[2];
    const float* c0     = (const float*)d_in[3];
    const float* eWih   = (const float*)d_in[4];
    const float* eWhh   = (const float*)d_in[5];
    const float* eb     = (const float*)d_in[6];
    const float* dWih   = (const float*)d_in[7];
    const float* dWhh   = (const float*)d_in[8];
    const float* db     = (const float*)d_in[9];
    const float* fcW    = (const float*)d_in[10];
    const float* fcb    = (const float*)d_in[11];
    float* out = (float*)d_out;

    const int smem_recur = (4096 + NCH * 2304) * 8;   // 106496 B
    cudaFuncSetAttribute(recur_kernel, cudaFuncAttributeMaxDynamicSharedMemorySize, smem_recur);

    init_state<<<128, 256>>>(h0, c0);

    float* genc; cudaGetSymbolAddress((void**)&genc, d_Genc);
    float* gdec; cudaGetSymbolAddress((void**)&gdec, d_Gdec);
    float* ghs;  cudaGetSymbolAddress((void**)&ghs,  d_hs);
    float* glog; cudaGetSymbolAddress((void**)&glog, d_logits);

    gemm_kernel<<<dim3(16, TSTEPS), 256>>>(x,      eWih, eb, genc, G4H, DIN, DIN / 32, 0, 0, 0);
    gemm_kernel<<<dim3(16, TSTEPS), 256>>>(target, dWih, db, gdec, G4H, DOUT, DOUT / 32, 1, 0, 0);

    recur_kernel<<<NBLK, 512, smem_recur>>>(eWhh, 0, 0);
    recur_kernel<<<NBLK, 512, smem_recur>>>(dWhh, 1, TSTEPS);

    gemm_kernel<<<dim3(2, TSTEPS), 256>>>(ghs, fcW, fcb, glog, DOUT, HID, HID / 32, 0, 1, 1);
    softmax_kernel<<<(TSTEPS * BATCH + 7) / 8, 256>>>(out);
}